// round 12
// baseline (speedup 1.0000x reference)
#include <cuda_runtime.h>
#include <cuda_bf16.h>
#include <cstdint>

#define L_LAYERS 4
#define R_COUNT  3
#define ZTOT     (L_LAYERS * R_COUNT)   // 12
#define BN_IMG   8
#define NPAIR    28                     // unordered image pairs b<c
#define PH       24
#define PW       24
#define P_N      576
#define D_N      1024
#define H_OUT    336
#define W_OUT    336
#define M_TOT    4608

// CTA tile: M=192 x N=192, K-chunk 128 bf16 stored as two 64-col panels
// (128B rows, SW128). 8 warps (2x4), warp tile 96x48. 2-stage double buffer,
// ONE barrier per chunk.
#define TM 192
#define TN 192
#define KC 128
#define PANEL       24576                    // 192 rows * 128B
#define A_BYTES     (2 * PANEL)              // 49152
#define STAGE_BYTES (2 * A_BYTES)            // 98304
#define SMEM_MAXES  (2 * STAGE_BYTES)        // 196608
#define SMEM_TOTAL  (SMEM_MAXES + (TM + TN) * 4)

// ---------------- scratch ----------------
__device__ __nv_bfloat16 g_fnorm[(size_t)ZTOT * M_TOT * D_N];        // 108 MB
__device__ unsigned int  g_dotmax[ZTOT * BN_IMG * P_N * BN_IMG];
__device__ float         g_scores[BN_IMG * P_N];

// ---------------- helpers ----------------
__device__ __forceinline__ uint32_t smem_u32(const void* p) {
    uint32_t a;
    asm("{ .reg .u64 t; cvta.to.shared.u64 t, %1; cvt.u32.u64 %0, t; }"
        : "=r"(a) : "l"(p));
    return a;
}
#define SWZ128(o) ((o) ^ (((o) >> 3) & 0x70))

__device__ __forceinline__ void cp16(uint32_t dst, const void* src) {
    asm volatile("cp.async.cg.shared.global [%0], [%1], 16;"
                 :: "r"(dst), "l"(src) : "memory");
}
__device__ __forceinline__ void ldsm_x4(uint32_t (&r)[4], uint32_t addr) {
    asm volatile("ldmatrix.sync.aligned.m8n8.x4.shared.b16 {%0,%1,%2,%3}, [%4];"
                 : "=r"(r[0]), "=r"(r[1]), "=r"(r[2]), "=r"(r[3]) : "r"(addr));
}
__device__ __forceinline__ void mma16816(float* d, const uint32_t* a, const uint32_t* b) {
    asm volatile("mma.sync.aligned.m16n8k16.row.col.f32.bf16.bf16.f32 "
                 "{%0,%1,%2,%3}, {%4,%5,%6,%7}, {%8,%9}, {%0,%1,%2,%3};"
                 : "+f"(d[0]), "+f"(d[1]), "+f"(d[2]), "+f"(d[3])
                 : "r"(a[0]), "r"(a[1]), "r"(a[2]), "r"(a[3]), "r"(b[0]), "r"(b[1]));
}
__device__ __forceinline__ unsigned enc_f(float v) {
    unsigned u = __float_as_uint(v);
    return (u & 0x80000000u) ? ~u : (u | 0x80000000u);
}

// ---------------- zero init ----------------
__global__ void zero_dot_kernel() {
    int i = blockIdx.x * blockDim.x + threadIdx.x;
    if (i < ZTOT * BN_IMG * P_N * BN_IMG) g_dotmax[i] = 0u;
}

// ---------------- fused pool (r=1,3,5) + normalize, sliding window --------
__device__ __forceinline__ void f4add(float4& a, const float4& f) {
    a.x += f.x; a.y += f.y; a.z += f.z; a.w += f.w;
}
__device__ __forceinline__ float f4dot(const float4& a) {
    return a.x * a.x + a.y * a.y + a.z * a.z + a.w * a.w;
}

__global__ void __launch_bounds__(256) pool_norm_fused(const float* __restrict__ feat) {
    __shared__ float sred[8 * 3];
    int bid = blockIdx.x;
    int l  = bid / (BN_IMG * PH);
    int rm = bid % (BN_IMG * PH);
    int b  = rm / PH;
    int py = rm % PH;
    const float* base = feat + (size_t)(l * BN_IMG + b) * P_N * D_N;

    int tid = threadIdx.x;
    int lane = tid & 31, w = tid >> 5;
    int d4 = tid * 4;

    float4 z4 = {0.f, 0.f, 0.f, 0.f};
    float4 ring5[5], ring3[5], ringc[5];
#pragma unroll
    for (int i = 0; i < 5; i++) { ring5[i] = z4; ring3[i] = z4; ringc[i] = z4; }

#pragma unroll
    for (int x = 0; x < PW + 2; x++) {        // px = x-2 in [0, PW)
        float4 c5 = z4, c3 = z4, cc = z4;
        if (x < PW) {
#pragma unroll
            for (int dy = -2; dy <= 2; dy++) {
                int y = py + dy;
                if (y < 0 || y >= PH) continue;
                float4 f = *(const float4*)&base[(size_t)(y * PW + x) * D_N + d4];
                f4add(c5, f);
                if (dy >= -1 && dy <= 1) f4add(c3, f);
                if (dy == 0) cc = f;
            }
        }
        ring5[x % 5] = c5; ring3[x % 5] = c3; ringc[x % 5] = cc;

        if (x >= 2) {
            int px = x - 2;
            float4 s5 = z4;
#pragma unroll
            for (int i = 0; i < 5; i++) f4add(s5, ring5[i]);
            float4 s3 = ring3[(x + 2) % 5];
            f4add(s3, ring3[(x + 3) % 5]);
            f4add(s3, ring3[(x + 4) % 5]);
            float4 s1 = ringc[(x + 3) % 5];

            float4 v3, v5;
            v3.x = s3.x * (1.f/9.f);  v3.y = s3.y * (1.f/9.f);
            v3.z = s3.z * (1.f/9.f);  v3.w = s3.w * (1.f/9.f);
            v5.x = s5.x * (1.f/25.f); v5.y = s5.y * (1.f/25.f);
            v5.z = s5.z * (1.f/25.f); v5.w = s5.w * (1.f/25.f);

            float q1 = f4dot(s1), q3 = f4dot(v3), q5 = f4dot(v5);
#pragma unroll
            for (int o = 16; o > 0; o >>= 1) {
                q1 += __shfl_xor_sync(0xffffffffu, q1, o);
                q3 += __shfl_xor_sync(0xffffffffu, q3, o);
                q5 += __shfl_xor_sync(0xffffffffu, q5, o);
            }
            if (lane == 0) { sred[w*3] = q1; sred[w*3+1] = q3; sred[w*3+2] = q5; }
            __syncthreads();
            float t1 = 0.f, t3 = 0.f, t5 = 0.f;
#pragma unroll
            for (int ww = 0; ww < 8; ww++) {
                t1 += sred[ww*3]; t3 += sred[ww*3+1]; t5 += sred[ww*3+2];
            }
            __syncthreads();
            float i1 = rsqrtf(t1), i3 = rsqrtf(t3), i5 = rsqrtf(t5);

            int row = b * P_N + py * PW + px;
            size_t off = (size_t)row * D_N + d4;
#pragma unroll
            for (int r = 0; r < 3; r++) {
                float4 v = (r == 0) ? s1 : (r == 1) ? v3 : v5;
                float sc = (r == 0) ? i1 : (r == 1) ? i3 : i5;
                __nv_bfloat162 lo(__float2bfloat16(v.x * sc), __float2bfloat16(v.y * sc));
                __nv_bfloat162 hi(__float2bfloat16(v.z * sc), __float2bfloat16(v.w * sc));
                uint2 pk;
                pk.x = *(uint32_t*)&lo; pk.y = *(uint32_t*)&hi;
                *(uint2*)(g_fnorm + (size_t)(r * L_LAYERS + l) * M_TOT * D_N + off) = pk;
            }
        }
    }
}

// ---------------- bf16 mma.sync GEMM over image pairs, fused row+col max --
__global__ void __launch_bounds__(256, 1) gemm_mma_kernel(int z0) {
    extern __shared__ char smem[];
    unsigned* maxes = (unsigned*)(smem + SMEM_MAXES);  // [0..TM) rowmax, [TM..TM+TN) colmax

    int bz = blockIdx.z;
    int pi = bz % NPAIR, z = z0 + bz / NPAIR;
    int b = 0;
    { int t = pi, rem = BN_IMG - 1;
      while (t >= rem) { t -= rem; rem--; b++; }
      pi = t; }
    int c = b + 1 + pi;

    int mt = blockIdx.y;    // 0..2
    int nt = blockIdx.x;    // 0..2

    const __nv_bfloat16* base = g_fnorm + (size_t)z * M_TOT * D_N;
    const __nv_bfloat16* Abase = base + (size_t)(b * P_N + mt * TM) * D_N;
    const __nv_bfloat16* Bbase = base + (size_t)(c * P_N + nt * TN) * D_N;

    int tid = threadIdx.x;
    int lane = tid & 31, wid = tid >> 5;
    int wm = wid >> 2, wn = wid & 3;       // 2 x 4 warp grid, warp tile 96x48
    uint32_t sbase = smem_u32(smem);

    for (int i = tid; i < TM + TN; i += 256) maxes[i] = 0u;

    float acc[6][6][4];
#pragma unroll
    for (int mi = 0; mi < 6; mi++)
#pragma unroll
        for (int ni = 0; ni < 6; ni++)
#pragma unroll
            for (int j = 0; j < 4; j++) acc[mi][ni][j] = 0.f;

    // one K=128 chunk = A[192x128] + B[192x128], each as two 64-col panels
    auto load_chunk = [&](int s, int k0) {
        uint32_t st = sbase + s * STAGE_BYTES;
#pragma unroll
        for (int it = 0; it < 24; it++) {
            int v = tid + it * 256;          // 0..6143
            if (v < 3072) {                  // A: 192 rows x 16 vec16
                int r = v >> 4, c16 = v & 15;
                uint32_t dst = st + (c16 >> 3) * PANEL
                             + SWZ128(r * 128 + (c16 & 7) * 16);
                cp16(dst, Abase + (size_t)r * D_N + k0 + c16 * 8);
            } else {
                int v2 = v - 3072;
                int r = v2 >> 4, c16 = v2 & 15;
                uint32_t dst = st + A_BYTES + (c16 >> 3) * PANEL
                             + SWZ128(r * 128 + (c16 & 7) * 16);
                cp16(dst, Bbase + (size_t)r * D_N + k0 + c16 * 8);
            }
        }
        asm volatile("cp.async.commit_group;" ::: "memory");
    };

    auto compute_chunk = [&](int s) {
        uint32_t stg = sbase + s * STAGE_BYTES;
        int arow = wm * 96 + (lane & 15);
        int aseg = (lane >> 4) * 16;
        int brow = wn * 48 + (lane & 7) + ((lane & 16) >> 1);   // x4 B
        int bseg = (lane & 8) * 2;
#pragma unroll
        for (int kk = 0; kk < 8; kk++) {
            uint32_t aB = stg + (kk >> 2) * PANEL;
            uint32_t bB = stg + A_BYTES + (kk >> 2) * PANEL;
            int kByte = (kk & 3) * 32;
            uint32_t a[6][4], bb[6][2];
#pragma unroll
            for (int mi = 0; mi < 6; mi++)
                ldsm_x4(a[mi], aB + SWZ128((arow + mi * 16) * 128 + kByte + aseg));
#pragma unroll
            for (int nj = 0; nj < 3; nj++) {
                uint32_t b4[4];
                ldsm_x4(b4, bB + SWZ128((brow + nj * 16) * 128 + kByte + bseg));
                bb[nj * 2][0] = b4[0]; bb[nj * 2][1] = b4[1];
                bb[nj * 2 + 1][0] = b4[2]; bb[nj * 2 + 1][1] = b4[3];
            }
#pragma unroll
            for (int mi = 0; mi < 6; mi++)
#pragma unroll
                for (int ni = 0; ni < 6; ni++)
                    mma16816(acc[mi][ni], a[mi], bb[ni]);
        }
    };

    // 2-stage, ONE barrier per chunk:
    //   wait(load kc) -> sync (all warps done computing chunk kc-1, which used
    //   stage cur^1) -> issue load kc+1 into cur^1 -> compute cur
    load_chunk(0, 0);
#pragma unroll 1
    for (int kc = 0; kc < 8; kc++) {
        int cur = kc & 1;
        asm volatile("cp.async.wait_group 0;" ::: "memory");
        __syncthreads();
        if (kc + 1 < 8) load_chunk(cur ^ 1, (kc + 1) * KC);
        compute_chunk(cur);
    }

    // ---- epilogue: row max over 192 cols, col max over 192 rows ----
#pragma unroll
    for (int mi = 0; mi < 6; mi++) {
        float rm0 = -1e30f, rm1 = -1e30f;
#pragma unroll
        for (int ni = 0; ni < 6; ni++) {
            rm0 = fmaxf(rm0, fmaxf(acc[mi][ni][0], acc[mi][ni][1]));
            rm1 = fmaxf(rm1, fmaxf(acc[mi][ni][2], acc[mi][ni][3]));
        }
        rm0 = fmaxf(rm0, __shfl_xor_sync(0xffffffffu, rm0, 1));
        rm0 = fmaxf(rm0, __shfl_xor_sync(0xffffffffu, rm0, 2));
        rm1 = fmaxf(rm1, __shfl_xor_sync(0xffffffffu, rm1, 1));
        rm1 = fmaxf(rm1, __shfl_xor_sync(0xffffffffu, rm1, 2));
        if ((lane & 3) == 0) {
            int r0 = wm * 96 + mi * 16 + (lane >> 2);
            atomicMax(&maxes[r0], enc_f(rm0));
            atomicMax(&maxes[r0 + 8], enc_f(rm1));
        }
    }
#pragma unroll
    for (int ni = 0; ni < 6; ni++) {
        float cm0 = -1e30f, cm1 = -1e30f;
#pragma unroll
        for (int mi = 0; mi < 6; mi++) {
            cm0 = fmaxf(cm0, fmaxf(acc[mi][ni][0], acc[mi][ni][2]));
            cm1 = fmaxf(cm1, fmaxf(acc[mi][ni][1], acc[mi][ni][3]));
        }
        cm0 = fmaxf(cm0, __shfl_xor_sync(0xffffffffu, cm0, 4));
        cm0 = fmaxf(cm0, __shfl_xor_sync(0xffffffffu, cm0, 8));
        cm0 = fmaxf(cm0, __shfl_xor_sync(0xffffffffu, cm0, 16));
        cm1 = fmaxf(cm1, __shfl_xor_sync(0xffffffffu, cm1, 4));
        cm1 = fmaxf(cm1, __shfl_xor_sync(0xffffffffu, cm1, 8));
        cm1 = fmaxf(cm1, __shfl_xor_sync(0xffffffffu, cm1, 16));
        if (lane < 4) {
            int c0 = wn * 48 + ni * 8 + lane * 2;
            atomicMax(&maxes[TM + c0], enc_f(cm0));
            atomicMax(&maxes[TM + c0 + 1], enc_f(cm1));
        }
    }
    __syncthreads();

    if (tid < TM) {
        int p = mt * TM + tid;
        atomicMax(&g_dotmax[((z * BN_IMG + b) * P_N + p) * BN_IMG + c], maxes[tid]);
        int q = nt * TN + tid;
        atomicMax(&g_dotmax[((z * BN_IMG + c) * P_N + q) * BN_IMG + b], maxes[TM + tid]);
    }
}

// ---------------- top-2-smallest over c!=b, mean over 12 (l,r) ----------
__global__ void reduce_kernel() {
    int idx = blockIdx.x * blockDim.x + threadIdx.x;
    if (idx >= BN_IMG * P_N) return;
    int b = idx / P_N, p = idx % P_N;
    float ssum = 0.f;
#pragma unroll
    for (int z = 0; z < ZTOT; z++) {
        float m1 = 1e30f, m2 = 1e30f;
#pragma unroll
        for (int c = 0; c < BN_IMG; c++) {
            if (c == b) continue;
            unsigned e = g_dotmax[((z * BN_IMG + b) * P_N + p) * BN_IMG + c];
            unsigned u = (e & 0x80000000u) ? (e & 0x7FFFFFFFu) : ~e;
            float dot = __uint_as_float(u);
            float d = sqrtf(fmaxf(2.f - 2.f * dot, 0.f));
            if (d < m1) { m2 = m1; m1 = d; }
            else if (d < m2) { m2 = d; }
        }
        ssum += 0.5f * (m1 + m2);
    }
    g_scores[idx] = ssum * (1.0f / (float)ZTOT);
}

// ---------------- outputs ----------------
__global__ void image_kernel(float* __restrict__ out) {
    int b = blockIdx.x;
    int tid = threadIdx.x;
    float mx = -1e30f;
    for (int p = tid; p < P_N; p += blockDim.x)
        mx = fmaxf(mx, g_scores[b * P_N + p]);
#pragma unroll
    for (int o = 16; o > 0; o >>= 1)
        mx = fmaxf(mx, __shfl_xor_sync(0xffffffffu, mx, o));
    __shared__ float wm[8];
    if ((tid & 31) == 0) wm[tid >> 5] = mx;
    __syncthreads();
    if (tid == 0) {
        float m = wm[0];
        for (int w = 1; w < (int)(blockDim.x >> 5); w++) m = fmaxf(m, wm[w]);
        out[b] = m;
    }
}

__global__ void pixel_kernel(float* __restrict__ out) {
    int idx = blockIdx.x * blockDim.x + threadIdx.x;
    int total = BN_IMG * H_OUT * W_OUT;
    if (idx >= total) return;
    int ox = idx % W_OUT;
    int oy = (idx / W_OUT) % H_OUT;
    int b  = idx / (H_OUT * W_OUT);

    const float sy = (float)(PH - 1) / (float)(H_OUT - 1);
    const float sx = (float)(PW - 1) / (float)(W_OUT - 1);
    float y = oy * sy, x = ox * sx;
    int y0 = (int)floorf(y); int y1 = min(y0 + 1, PH - 1);
    int x0 = (int)floorf(x); int x1 = min(x0 + 1, PW - 1);
    float wy = y - (float)y0, wx = x - (float)x0;

    const float* s = g_scores + b * P_N;
    float f00 = s[y0 * PW + x0], f01 = s[y0 * PW + x1];
    float f10 = s[y1 * PW + x0], f11 = s[y1 * PW + x1];
    float v = f00 * (1.f - wy) * (1.f - wx) + f01 * (1.f - wy) * wx
            + f10 * wy * (1.f - wx)         + f11 * wy * wx;
    out[BN_IMG + idx] = v;
}

// ---------------- driver ----------------
extern "C" void kernel_launch(void* const* d_in, const int* in_sizes, int n_in,
                              void* d_out, int out_size) {
    (void)in_sizes; (void)n_in; (void)out_size;
    const float* feat = (const float*)d_in[0];
    float* out = (float*)d_out;

    cudaFuncSetAttribute(gemm_mma_kernel,
                         cudaFuncAttributeMaxDynamicSharedMemorySize, SMEM_TOTAL);

    zero_dot_kernel<<<(ZTOT * BN_IMG * P_N * BN_IMG + 255) / 256, 256>>>();
    pool_norm_fused<<<L_LAYERS * BN_IMG * PH, 256>>>(feat);

    // 2 launches (6 z each); 2nd lands in the ncu capture slot
    gemm_mma_kernel<<<dim3(P_N / TN, P_N / TM, 6 * NPAIR), 256, SMEM_TOTAL>>>(0);
    gemm_mma_kernel<<<dim3(P_N / TN, P_N / TM, 6 * NPAIR), 256, SMEM_TOTAL>>>(6);

    reduce_kernel<<<(BN_IMG * P_N + 255) / 256, 256>>>();
    image_kernel<<<BN_IMG, 256>>>(out);
    pixel_kernel<<<(BN_IMG * H_OUT * W_OUT + 255) / 256, 256>>>(out);
}

// round 13
// speedup vs baseline: 1.0135x; 1.0135x over previous
#include <cuda_runtime.h>
#include <cuda_bf16.h>
#include <cstdint>

#define L_LAYERS 4
#define R_COUNT  3
#define ZTOT     (L_LAYERS * R_COUNT)   // 12
#define BN_IMG   8
#define NPAIR    28                     // unordered image pairs b<c
#define PH       24
#define PW       24
#define P_N      576
#define D_N      1024
#define H_OUT    336
#define W_OUT    336
#define M_TOT    4608

// CTA tile: M=192 x N=192, K-chunk 128 bf16 stored as two 64-col panels
// (128B rows, SW128). 8 warps (2x4), warp tile 96x48. 2-stage double buffer,
// R11 schedule (issue-load -> wait_group 1 -> sync -> compute -> sync).
#define TM 192
#define TN 192
#define KC 128
#define PANEL       24576                    // 192 rows * 128B
#define A_BYTES     (2 * PANEL)              // 49152
#define STAGE_BYTES (2 * A_BYTES)            // 98304
#define SMEM_TOTAL  (2 * STAGE_BYTES)        // 196608

// ---------------- scratch ----------------
__device__ __nv_bfloat16 g_fnorm[(size_t)ZTOT * M_TOT * D_N];        // 108 MB
__device__ unsigned int  g_dotmax[ZTOT * BN_IMG * P_N * BN_IMG];
__device__ float         g_scores[BN_IMG * P_N];

// ---------------- helpers ----------------
__device__ __forceinline__ uint32_t smem_u32(const void* p) {
    uint32_t a;
    asm("{ .reg .u64 t; cvta.to.shared.u64 t, %1; cvt.u32.u64 %0, t; }"
        : "=r"(a) : "l"(p));
    return a;
}
#define SWZ128(o) ((o) ^ (((o) >> 3) & 0x70))

__device__ __forceinline__ void cp16(uint32_t dst, const void* src) {
    asm volatile("cp.async.cg.shared.global [%0], [%1], 16;"
                 :: "r"(dst), "l"(src) : "memory");
}
__device__ __forceinline__ void ldsm_x4(uint32_t (&r)[4], uint32_t addr) {
    asm volatile("ldmatrix.sync.aligned.m8n8.x4.shared.b16 {%0,%1,%2,%3}, [%4];"
                 : "=r"(r[0]), "=r"(r[1]), "=r"(r[2]), "=r"(r[3]) : "r"(addr));
}
__device__ __forceinline__ void mma16816(float* d, const uint32_t* a, const uint32_t* b) {
    asm volatile("mma.sync.aligned.m16n8k16.row.col.f32.bf16.bf16.f32 "
                 "{%0,%1,%2,%3}, {%4,%5,%6,%7}, {%8,%9}, {%0,%1,%2,%3};"
                 : "+f"(d[0]), "+f"(d[1]), "+f"(d[2]), "+f"(d[3])
                 : "r"(a[0]), "r"(a[1]), "r"(a[2]), "r"(a[3]), "r"(b[0]), "r"(b[1]));
}
__device__ __forceinline__ unsigned enc_f(float v) {
    unsigned u = __float_as_uint(v);
    return (u & 0x80000000u) ? ~u : (u | 0x80000000u);
}

// ---------------- fused pool (r=1,3,5) + normalize + dotmax zeroing ------
__device__ __forceinline__ void f4add(float4& a, const float4& f) {
    a.x += f.x; a.y += f.y; a.z += f.z; a.w += f.w;
}
__device__ __forceinline__ float f4dot(const float4& a) {
    return a.x * a.x + a.y * a.y + a.z * a.z + a.w * a.w;
}

__global__ void __launch_bounds__(256) pool_norm_fused(const float* __restrict__ feat) {
    __shared__ float sred[2][8 * 3];
    int bid = blockIdx.x;

    // fold zero_dot: each of 768 blocks zeroes its 576-entry slice
    {
        int zbase = bid * (ZTOT * BN_IMG * P_N * BN_IMG / (L_LAYERS * BN_IMG * PH));
        for (int i = threadIdx.x; i < ZTOT * BN_IMG * P_N * BN_IMG / (L_LAYERS * BN_IMG * PH); i += 256)
            g_dotmax[zbase + i] = 0u;
    }

    int l  = bid / (BN_IMG * PH);
    int rm = bid % (BN_IMG * PH);
    int b  = rm / PH;
    int py = rm % PH;
    const float* base = feat + (size_t)(l * BN_IMG + b) * P_N * D_N;

    int tid = threadIdx.x;
    int lane = tid & 31, w = tid >> 5;
    int d4 = tid * 4;

    float4 z4 = {0.f, 0.f, 0.f, 0.f};
    float4 ring5[5], ring3[5], ringc[5];
#pragma unroll
    for (int i = 0; i < 5; i++) { ring5[i] = z4; ring3[i] = z4; ringc[i] = z4; }

#pragma unroll
    for (int x = 0; x < PW + 2; x++) {        // px = x-2 in [0, PW)
        float4 c5 = z4, c3 = z4, cc = z4;
        if (x < PW) {
#pragma unroll
            for (int dy = -2; dy <= 2; dy++) {
                int y = py + dy;
                if (y < 0 || y >= PH) continue;
                float4 f = *(const float4*)&base[(size_t)(y * PW + x) * D_N + d4];
                f4add(c5, f);
                if (dy >= -1 && dy <= 1) f4add(c3, f);
                if (dy == 0) cc = f;
            }
        }
        ring5[x % 5] = c5; ring3[x % 5] = c3; ringc[x % 5] = cc;

        if (x >= 2) {
            int px = x - 2;
            int buf = x & 1;
            float4 s5 = z4;
#pragma unroll
            for (int i = 0; i < 5; i++) f4add(s5, ring5[i]);
            float4 s3 = ring3[(x + 2) % 5];
            f4add(s3, ring3[(x + 3) % 5]);
            f4add(s3, ring3[(x + 4) % 5]);
            float4 s1 = ringc[(x + 3) % 5];

            float4 v3, v5;
            v3.x = s3.x * (1.f/9.f);  v3.y = s3.y * (1.f/9.f);
            v3.z = s3.z * (1.f/9.f);  v3.w = s3.w * (1.f/9.f);
            v5.x = s5.x * (1.f/25.f); v5.y = s5.y * (1.f/25.f);
            v5.z = s5.z * (1.f/25.f); v5.w = s5.w * (1.f/25.f);

            float q1 = f4dot(s1), q3 = f4dot(v3), q5 = f4dot(v5);
#pragma unroll
            for (int o = 16; o > 0; o >>= 1) {
                q1 += __shfl_xor_sync(0xffffffffu, q1, o);
                q3 += __shfl_xor_sync(0xffffffffu, q3, o);
                q5 += __shfl_xor_sync(0xffffffffu, q5, o);
            }
            if (lane == 0) { sred[buf][w*3] = q1; sred[buf][w*3+1] = q3; sred[buf][w*3+2] = q5; }
            __syncthreads();      // single barrier; buffers alternate by x parity
            float t1 = 0.f, t3 = 0.f, t5 = 0.f;
#pragma unroll
            for (int ww = 0; ww < 8; ww++) {
                t1 += sred[buf][ww*3]; t3 += sred[buf][ww*3+1]; t5 += sred[buf][ww*3+2];
            }
            float i1 = rsqrtf(t1), i3 = rsqrtf(t3), i5 = rsqrtf(t5);

            int row = b * P_N + py * PW + px;
            size_t off = (size_t)row * D_N + d4;
#pragma unroll
            for (int r = 0; r < 3; r++) {
                float4 v = (r == 0) ? s1 : (r == 1) ? v3 : v5;
                float sc = (r == 0) ? i1 : (r == 1) ? i3 : i5;
                __nv_bfloat162 lo(__float2bfloat16(v.x * sc), __float2bfloat16(v.y * sc));
                __nv_bfloat162 hi(__float2bfloat16(v.z * sc), __float2bfloat16(v.w * sc));
                uint2 pk;
                pk.x = *(uint32_t*)&lo; pk.y = *(uint32_t*)&hi;
                *(uint2*)(g_fnorm + (size_t)(r * L_LAYERS + l) * M_TOT * D_N + off) = pk;
            }
        }
    }
}

// ---------------- bf16 mma.sync GEMM over image pairs, fused row+col max --
__global__ void __launch_bounds__(256, 1) gemm_mma_kernel(int z0) {
    extern __shared__ char smem[];

    int bz = blockIdx.z;
    int pi = bz % NPAIR, z = z0 + bz / NPAIR;
    int b = 0;
    { int t = pi, rem = BN_IMG - 1;
      while (t >= rem) { t -= rem; rem--; b++; }
      pi = t; }
    int c = b + 1 + pi;

    int mt = blockIdx.y;    // 0..2
    int nt = blockIdx.x;    // 0..2

    const __nv_bfloat16* base = g_fnorm + (size_t)z * M_TOT * D_N;
    const __nv_bfloat16* Abase = base + (size_t)(b * P_N + mt * TM) * D_N;
    const __nv_bfloat16* Bbase = base + (size_t)(c * P_N + nt * TN) * D_N;

    int tid = threadIdx.x;
    int lane = tid & 31, wid = tid >> 5;
    int wm = wid >> 2, wn = wid & 3;       // 2 x 4 warp grid, warp tile 96x48
    uint32_t sbase = smem_u32(smem);

    float acc[6][6][4];
#pragma unroll
    for (int mi = 0; mi < 6; mi++)
#pragma unroll
        for (int ni = 0; ni < 6; ni++)
#pragma unroll
            for (int j = 0; j < 4; j++) acc[mi][ni][j] = 0.f;

    // one K=128 chunk = A[192x128] + B[192x128], each as two 64-col panels
    auto load_chunk = [&](int s, int k0) {
        uint32_t st = sbase + s * STAGE_BYTES;
#pragma unroll
        for (int it = 0; it < 24; it++) {
            int v = tid + it * 256;          // 0..6143
            if (v < 3072) {                  // A: 192 rows x 16 vec16
                int r = v >> 4, c16 = v & 15;
                uint32_t dst = st + (c16 >> 3) * PANEL
                             + SWZ128(r * 128 + (c16 & 7) * 16);
                cp16(dst, Abase + (size_t)r * D_N + k0 + c16 * 8);
            } else {
                int v2 = v - 3072;
                int r = v2 >> 4, c16 = v2 & 15;
                uint32_t dst = st + A_BYTES + (c16 >> 3) * PANEL
                             + SWZ128(r * 128 + (c16 & 7) * 16);
                cp16(dst, Bbase + (size_t)r * D_N + k0 + c16 * 8);
            }
        }
        asm volatile("cp.async.commit_group;" ::: "memory");
    };

    auto compute_chunk = [&](int s) {
        uint32_t stg = sbase + s * STAGE_BYTES;
        int arow = wm * 96 + (lane & 15);
        int aseg = (lane >> 4) * 16;
        int brow = wn * 48 + (lane & 7) + ((lane & 16) >> 1);   // x4 B
        int bseg = (lane & 8) * 2;
#pragma unroll
        for (int kk = 0; kk < 8; kk++) {
            uint32_t aB = stg + (kk >> 2) * PANEL;
            uint32_t bB = stg + A_BYTES + (kk >> 2) * PANEL;
            int kByte = (kk & 3) * 32;
            uint32_t a[6][4], bb[6][2];
#pragma unroll
            for (int mi = 0; mi < 6; mi++)
                ldsm_x4(a[mi], aB + SWZ128((arow + mi * 16) * 128 + kByte + aseg));
#pragma unroll
            for (int nj = 0; nj < 3; nj++) {
                uint32_t b4[4];
                ldsm_x4(b4, bB + SWZ128((brow + nj * 16) * 128 + kByte + bseg));
                bb[nj * 2][0] = b4[0]; bb[nj * 2][1] = b4[1];
                bb[nj * 2 + 1][0] = b4[2]; bb[nj * 2 + 1][1] = b4[3];
            }
#pragma unroll
            for (int mi = 0; mi < 6; mi++)
#pragma unroll
                for (int ni = 0; ni < 6; ni++)
                    mma16816(acc[mi][ni], a[mi], bb[ni]);
        }
    };

    // R11 schedule: issue next load, keep 1 group in flight across the barrier
    load_chunk(0, 0);
#pragma unroll 1
    for (int kc = 0; kc < 8; kc++) {
        int cur = kc & 1;
        if (kc + 1 < 8) {
            load_chunk(cur ^ 1, (kc + 1) * KC);
            asm volatile("cp.async.wait_group 1;" ::: "memory");
        } else {
            asm volatile("cp.async.wait_group 0;" ::: "memory");
        }
        __syncthreads();
        compute_chunk(cur);
        __syncthreads();
    }

    // ---- epilogue: direct global atomics (no smem staging) ----
    unsigned* rowdst = &g_dotmax[((z * BN_IMG + b) * P_N) * BN_IMG + c];
    unsigned* coldst = &g_dotmax[((z * BN_IMG + c) * P_N) * BN_IMG + b];
#pragma unroll
    for (int mi = 0; mi < 6; mi++) {
        float rm0 = -1e30f, rm1 = -1e30f;
#pragma unroll
        for (int ni = 0; ni < 6; ni++) {
            rm0 = fmaxf(rm0, fmaxf(acc[mi][ni][0], acc[mi][ni][1]));
            rm1 = fmaxf(rm1, fmaxf(acc[mi][ni][2], acc[mi][ni][3]));
        }
        rm0 = fmaxf(rm0, __shfl_xor_sync(0xffffffffu, rm0, 1));
        rm0 = fmaxf(rm0, __shfl_xor_sync(0xffffffffu, rm0, 2));
        rm1 = fmaxf(rm1, __shfl_xor_sync(0xffffffffu, rm1, 1));
        rm1 = fmaxf(rm1, __shfl_xor_sync(0xffffffffu, rm1, 2));
        if ((lane & 3) == 0) {
            int r0 = wm * 96 + mi * 16 + (lane >> 2);
            int p0 = mt * TM + r0;
            atomicMax(rowdst + p0 * BN_IMG, enc_f(rm0));
            atomicMax(rowdst + (p0 + 8) * BN_IMG, enc_f(rm1));
        }
    }
#pragma unroll
    for (int ni = 0; ni < 6; ni++) {
        float cm0 = -1e30f, cm1 = -1e30f;
#pragma unroll
        for (int mi = 0; mi < 6; mi++) {
            cm0 = fmaxf(cm0, fmaxf(acc[mi][ni][0], acc[mi][ni][2]));
            cm1 = fmaxf(cm1, fmaxf(acc[mi][ni][1], acc[mi][ni][3]));
        }
        cm0 = fmaxf(cm0, __shfl_xor_sync(0xffffffffu, cm0, 4));
        cm0 = fmaxf(cm0, __shfl_xor_sync(0xffffffffu, cm0, 8));
        cm0 = fmaxf(cm0, __shfl_xor_sync(0xffffffffu, cm0, 16));
        cm1 = fmaxf(cm1, __shfl_xor_sync(0xffffffffu, cm1, 4));
        cm1 = fmaxf(cm1, __shfl_xor_sync(0xffffffffu, cm1, 8));
        cm1 = fmaxf(cm1, __shfl_xor_sync(0xffffffffu, cm1, 16));
        if (lane < 4) {
            int q0 = nt * TN + wn * 48 + ni * 8 + lane * 2;
            atomicMax(coldst + q0 * BN_IMG, enc_f(cm0));
            atomicMax(coldst + (q0 + 1) * BN_IMG, enc_f(cm1));
        }
    }
}

// ---------------- top-2-smallest over c!=b, mean over 12 (l,r) ----------
__global__ void reduce_kernel() {
    int idx = blockIdx.x * blockDim.x + threadIdx.x;
    if (idx >= BN_IMG * P_N) return;
    int b = idx / P_N, p = idx % P_N;
    float ssum = 0.f;
#pragma unroll
    for (int z = 0; z < ZTOT; z++) {
        float m1 = 1e30f, m2 = 1e30f;
#pragma unroll
        for (int c = 0; c < BN_IMG; c++) {
            if (c == b) continue;
            unsigned e = g_dotmax[((z * BN_IMG + b) * P_N + p) * BN_IMG + c];
            unsigned u = (e & 0x80000000u) ? (e & 0x7FFFFFFFu) : ~e;
            float dot = __uint_as_float(u);
            float d = sqrtf(fmaxf(2.f - 2.f * dot, 0.f));
            if (d < m1) { m2 = m1; m1 = d; }
            else if (d < m2) { m2 = d; }
        }
        ssum += 0.5f * (m1 + m2);
    }
    g_scores[idx] = ssum * (1.0f / (float)ZTOT);
}

// ---------------- outputs ----------------
__global__ void image_kernel(float* __restrict__ out) {
    int b = blockIdx.x;
    int tid = threadIdx.x;
    float mx = -1e30f;
    for (int p = tid; p < P_N; p += blockDim.x)
        mx = fmaxf(mx, g_scores[b * P_N + p]);
#pragma unroll
    for (int o = 16; o > 0; o >>= 1)
        mx = fmaxf(mx, __shfl_xor_sync(0xffffffffu, mx, o));
    __shared__ float wm[8];
    if ((tid & 31) == 0) wm[tid >> 5] = mx;
    __syncthreads();
    if (tid == 0) {
        float m = wm[0];
        for (int w = 1; w < (int)(blockDim.x >> 5); w++) m = fmaxf(m, wm[w]);
        out[b] = m;
    }
}

__global__ void pixel_kernel(float* __restrict__ out) {
    int idx = blockIdx.x * blockDim.x + threadIdx.x;
    int total = BN_IMG * H_OUT * W_OUT;
    if (idx >= total) return;
    int ox = idx % W_OUT;
    int oy = (idx / W_OUT) % H_OUT;
    int b  = idx / (H_OUT * W_OUT);

    const float sy = (float)(PH - 1) / (float)(H_OUT - 1);
    const float sx = (float)(PW - 1) / (float)(W_OUT - 1);
    float y = oy * sy, x = ox * sx;
    int y0 = (int)floorf(y); int y1 = min(y0 + 1, PH - 1);
    int x0 = (int)floorf(x); int x1 = min(x0 + 1, PW - 1);
    float wy = y - (float)y0, wx = x - (float)x0;

    const float* s = g_scores + b * P_N;
    float f00 = s[y0 * PW + x0], f01 = s[y0 * PW + x1];
    float f10 = s[y1 * PW + x0], f11 = s[y1 * PW + x1];
    float v = f00 * (1.f - wy) * (1.f - wx) + f01 * (1.f - wy) * wx
            + f10 * wy * (1.f - wx)         + f11 * wy * wx;
    out[BN_IMG + idx] = v;
}

// ---------------- driver ----------------
extern "C" void kernel_launch(void* const* d_in, const int* in_sizes, int n_in,
                              void* d_out, int out_size) {
    (void)in_sizes; (void)n_in; (void)out_size;
    const float* feat = (const float*)d_in[0];
    float* out = (float*)d_out;

    cudaFuncSetAttribute(gemm_mma_kernel,
                         cudaFuncAttributeMaxDynamicSharedMemorySize, SMEM_TOTAL);

    pool_norm_fused<<<L_LAYERS * BN_IMG * PH, 256>>>(feat);

    // 2 launches (6 z each)
    gemm_mma_kernel<<<dim3(P_N / TN, P_N / TM, 6 * NPAIR), 256, SMEM_TOTAL>>>(0);
    gemm_mma_kernel<<<dim3(P_N / TN, P_N / TM, 6 * NPAIR), 256, SMEM_TOTAL>>>(6);

    reduce_kernel<<<(BN_IMG * P_N + 255) / 256, 256>>>();
    image_kernel<<<BN_IMG, 256>>>(out);
    pixel_kernel<<<(BN_IMG * H_OUT * W_OUT + 255) / 256, 256>>>(out);
}

// round 14
// speedup vs baseline: 1.0451x; 1.0312x over previous
#include <cuda_runtime.h>
#include <cuda_bf16.h>
#include <cstdint>

#define L_LAYERS 4
#define R_COUNT  3
#define ZTOT     (L_LAYERS * R_COUNT)   // 12
#define BN_IMG   8
#define NPAIR    28                     // unordered image pairs b<c
#define PH       24
#define PW       24
#define P_N      576
#define D_N      1024
#define H_OUT    336
#define W_OUT    336
#define M_TOT    4608

// CTA tile: M=192 x N=192, K-chunk 128 bf16 stored as two 64-col panels
// (128B rows, SW128). 8 warps (2x4), warp tile 96x48. 2-stage double buffer,
// R11 schedule (issue-load -> wait_group 1 -> sync -> compute -> sync).
#define TM 192
#define TN 192
#define KC 128
#define PANEL       24576                    // 192 rows * 128B
#define A_BYTES     (2 * PANEL)              // 49152
#define STAGE_BYTES (2 * A_BYTES)            // 98304
#define SMEM_MAXES  (2 * STAGE_BYTES)        // 196608
#define SMEM_TOTAL  (SMEM_MAXES + (TM + TN) * 4)

// ---------------- scratch ----------------
__device__ __nv_bfloat16 g_fnorm[(size_t)ZTOT * M_TOT * D_N];        // 108 MB
__device__ unsigned int  g_dotmax[ZTOT * BN_IMG * P_N * BN_IMG];
__device__ float         g_scores[BN_IMG * P_N];

// ---------------- helpers ----------------
__device__ __forceinline__ uint32_t smem_u32(const void* p) {
    uint32_t a;
    asm("{ .reg .u64 t; cvta.to.shared.u64 t, %1; cvt.u32.u64 %0, t; }"
        : "=r"(a) : "l"(p));
    return a;
}
#define SWZ128(o) ((o) ^ (((o) >> 3) & 0x70))

__device__ __forceinline__ void cp16(uint32_t dst, const void* src) {
    asm volatile("cp.async.cg.shared.global [%0], [%1], 16;"
                 :: "r"(dst), "l"(src) : "memory");
}
__device__ __forceinline__ void ldsm_x4(uint32_t (&r)[4], uint32_t addr) {
    asm volatile("ldmatrix.sync.aligned.m8n8.x4.shared.b16 {%0,%1,%2,%3}, [%4];"
                 : "=r"(r[0]), "=r"(r[1]), "=r"(r[2]), "=r"(r[3]) : "r"(addr));
}
__device__ __forceinline__ void mma16816(float* d, const uint32_t* a, const uint32_t* b) {
    asm volatile("mma.sync.aligned.m16n8k16.row.col.f32.bf16.bf16.f32 "
                 "{%0,%1,%2,%3}, {%4,%5,%6,%7}, {%8,%9}, {%0,%1,%2,%3};"
                 : "+f"(d[0]), "+f"(d[1]), "+f"(d[2]), "+f"(d[3])
                 : "r"(a[0]), "r"(a[1]), "r"(a[2]), "r"(a[3]), "r"(b[0]), "r"(b[1]));
}
__device__ __forceinline__ unsigned enc_f(float v) {
    unsigned u = __float_as_uint(v);
    return (u & 0x80000000u) ? ~u : (u | 0x80000000u);
}

// ---------------- zero init (dotmax + scores) ----------------
__global__ void zero_dot_kernel() {
    int i = blockIdx.x * blockDim.x + threadIdx.x;
    if (i < ZTOT * BN_IMG * P_N * BN_IMG) g_dotmax[i] = 0u;
    if (i < BN_IMG * P_N) g_scores[i] = 0.f;
}

// ---------------- fused pool (r=1,3,5) + normalize, sliding window --------
__device__ __forceinline__ void f4add(float4& a, const float4& f) {
    a.x += f.x; a.y += f.y; a.z += f.z; a.w += f.w;
}
__device__ __forceinline__ float f4dot(const float4& a) {
    return a.x * a.x + a.y * a.y + a.z * a.z + a.w * a.w;
}

__global__ void __launch_bounds__(256) pool_norm_fused(const float* __restrict__ feat) {
    __shared__ float sred[8 * 3];
    int bid = blockIdx.x;
    int l  = bid / (BN_IMG * PH);
    int rm = bid % (BN_IMG * PH);
    int b  = rm / PH;
    int py = rm % PH;
    const float* base = feat + (size_t)(l * BN_IMG + b) * P_N * D_N;

    int tid = threadIdx.x;
    int lane = tid & 31, w = tid >> 5;
    int d4 = tid * 4;

    float4 z4 = {0.f, 0.f, 0.f, 0.f};
    float4 ring5[5], ring3[5], ringc[5];
#pragma unroll
    for (int i = 0; i < 5; i++) { ring5[i] = z4; ring3[i] = z4; ringc[i] = z4; }

#pragma unroll
    for (int x = 0; x < PW + 2; x++) {        // px = x-2 in [0, PW)
        float4 c5 = z4, c3 = z4, cc = z4;
        if (x < PW) {
#pragma unroll
            for (int dy = -2; dy <= 2; dy++) {
                int y = py + dy;
                if (y < 0 || y >= PH) continue;
                float4 f = *(const float4*)&base[(size_t)(y * PW + x) * D_N + d4];
                f4add(c5, f);
                if (dy >= -1 && dy <= 1) f4add(c3, f);
                if (dy == 0) cc = f;
            }
        }
        ring5[x % 5] = c5; ring3[x % 5] = c3; ringc[x % 5] = cc;

        if (x >= 2) {
            int px = x - 2;
            float4 s5 = z4;
#pragma unroll
            for (int i = 0; i < 5; i++) f4add(s5, ring5[i]);
            float4 s3 = ring3[(x + 2) % 5];
            f4add(s3, ring3[(x + 3) % 5]);
            f4add(s3, ring3[(x + 4) % 5]);
            float4 s1 = ringc[(x + 3) % 5];

            float4 v3, v5;
            v3.x = s3.x * (1.f/9.f);  v3.y = s3.y * (1.f/9.f);
            v3.z = s3.z * (1.f/9.f);  v3.w = s3.w * (1.f/9.f);
            v5.x = s5.x * (1.f/25.f); v5.y = s5.y * (1.f/25.f);
            v5.z = s5.z * (1.f/25.f); v5.w = s5.w * (1.f/25.f);

            float q1 = f4dot(s1), q3 = f4dot(v3), q5 = f4dot(v5);
#pragma unroll
            for (int o = 16; o > 0; o >>= 1) {
                q1 += __shfl_xor_sync(0xffffffffu, q1, o);
                q3 += __shfl_xor_sync(0xffffffffu, q3, o);
                q5 += __shfl_xor_sync(0xffffffffu, q5, o);
            }
            if (lane == 0) { sred[w*3] = q1; sred[w*3+1] = q3; sred[w*3+2] = q5; }
            __syncthreads();
            float t1 = 0.f, t3 = 0.f, t5 = 0.f;
#pragma unroll
            for (int ww = 0; ww < 8; ww++) {
                t1 += sred[ww*3]; t3 += sred[ww*3+1]; t5 += sred[ww*3+2];
            }
            __syncthreads();
            float i1 = rsqrtf(t1), i3 = rsqrtf(t3), i5 = rsqrtf(t5);

            int row = b * P_N + py * PW + px;
            size_t off = (size_t)row * D_N + d4;
#pragma unroll
            for (int r = 0; r < 3; r++) {
                float4 v = (r == 0) ? s1 : (r == 1) ? v3 : v5;
                float sc = (r == 0) ? i1 : (r == 1) ? i3 : i5;
                __nv_bfloat162 lo(__float2bfloat16(v.x * sc), __float2bfloat16(v.y * sc));
                __nv_bfloat162 hi(__float2bfloat16(v.z * sc), __float2bfloat16(v.w * sc));
                uint2 pk;
                pk.x = *(uint32_t*)&lo; pk.y = *(uint32_t*)&hi;
                *(uint2*)(g_fnorm + (size_t)(r * L_LAYERS + l) * M_TOT * D_N + off) = pk;
            }
        }
    }
}

// ---------------- bf16 mma.sync GEMM over image pairs, fused row+col max --
__global__ void __launch_bounds__(256, 1) gemm_mma_kernel(int z0) {
    extern __shared__ char smem[];
    unsigned* maxes = (unsigned*)(smem + SMEM_MAXES);  // [0..TM) rowmax, [TM..TM+TN) colmax

    int bz = blockIdx.z;
    int pi = bz % NPAIR, z = z0 + bz / NPAIR;
    int b = 0;
    { int t = pi, rem = BN_IMG - 1;
      while (t >= rem) { t -= rem; rem--; b++; }
      pi = t; }
    int c = b + 1 + pi;

    int mt = blockIdx.y;    // 0..2
    int nt = blockIdx.x;    // 0..2

    const __nv_bfloat16* base = g_fnorm + (size_t)z * M_TOT * D_N;
    const __nv_bfloat16* Abase = base + (size_t)(b * P_N + mt * TM) * D_N;
    const __nv_bfloat16* Bbase = base + (size_t)(c * P_N + nt * TN) * D_N;

    int tid = threadIdx.x;
    int lane = tid & 31, wid = tid >> 5;
    int wm = wid >> 2, wn = wid & 3;       // 2 x 4 warp grid, warp tile 96x48
    uint32_t sbase = smem_u32(smem);

    for (int i = tid; i < TM + TN; i += 256) maxes[i] = 0u;

    float acc[6][6][4];
#pragma unroll
    for (int mi = 0; mi < 6; mi++)
#pragma unroll
        for (int ni = 0; ni < 6; ni++)
#pragma unroll
            for (int j = 0; j < 4; j++) acc[mi][ni][j] = 0.f;

    // one K=128 chunk = A[192x128] + B[192x128], each as two 64-col panels
    auto load_chunk = [&](int s, int k0) {
        uint32_t st = sbase + s * STAGE_BYTES;
#pragma unroll
        for (int it = 0; it < 24; it++) {
            int v = tid + it * 256;          // 0..6143
            if (v < 3072) {                  // A: 192 rows x 16 vec16
                int r = v >> 4, c16 = v & 15;
                uint32_t dst = st + (c16 >> 3) * PANEL
                             + SWZ128(r * 128 + (c16 & 7) * 16);
                cp16(dst, Abase + (size_t)r * D_N + k0 + c16 * 8);
            } else {
                int v2 = v - 3072;
                int r = v2 >> 4, c16 = v2 & 15;
                uint32_t dst = st + A_BYTES + (c16 >> 3) * PANEL
                             + SWZ128(r * 128 + (c16 & 7) * 16);
                cp16(dst, Bbase + (size_t)r * D_N + k0 + c16 * 8);
            }
        }
        asm volatile("cp.async.commit_group;" ::: "memory");
    };

    auto compute_chunk = [&](int s) {
        uint32_t stg = sbase + s * STAGE_BYTES;
        int arow = wm * 96 + (lane & 15);
        int aseg = (lane >> 4) * 16;
        int brow = wn * 48 + (lane & 7) + ((lane & 16) >> 1);   // x4 B
        int bseg = (lane & 8) * 2;
#pragma unroll
        for (int kk = 0; kk < 8; kk++) {
            uint32_t aB = stg + (kk >> 2) * PANEL;
            uint32_t bB = stg + A_BYTES + (kk >> 2) * PANEL;
            int kByte = (kk & 3) * 32;
            uint32_t a[6][4], bb[6][2];
#pragma unroll
            for (int mi = 0; mi < 6; mi++)
                ldsm_x4(a[mi], aB + SWZ128((arow + mi * 16) * 128 + kByte + aseg));
#pragma unroll
            for (int nj = 0; nj < 3; nj++) {
                uint32_t b4[4];
                ldsm_x4(b4, bB + SWZ128((brow + nj * 16) * 128 + kByte + bseg));
                bb[nj * 2][0] = b4[0]; bb[nj * 2][1] = b4[1];
                bb[nj * 2 + 1][0] = b4[2]; bb[nj * 2 + 1][1] = b4[3];
            }
#pragma unroll
            for (int mi = 0; mi < 6; mi++)
#pragma unroll
                for (int ni = 0; ni < 6; ni++)
                    mma16816(acc[mi][ni], a[mi], bb[ni]);
        }
    };

    // R11 schedule: issue next load, keep 1 group in flight across the barrier
    load_chunk(0, 0);
#pragma unroll 1
    for (int kc = 0; kc < 8; kc++) {
        int cur = kc & 1;
        if (kc + 1 < 8) {
            load_chunk(cur ^ 1, (kc + 1) * KC);
            asm volatile("cp.async.wait_group 1;" ::: "memory");
        } else {
            asm volatile("cp.async.wait_group 0;" ::: "memory");
        }
        __syncthreads();
        compute_chunk(cur);
        __syncthreads();
    }

    // ---- epilogue: row max over 192 cols, col max over 192 rows ----
#pragma unroll
    for (int mi = 0; mi < 6; mi++) {
        float rm0 = -1e30f, rm1 = -1e30f;
#pragma unroll
        for (int ni = 0; ni < 6; ni++) {
            rm0 = fmaxf(rm0, fmaxf(acc[mi][ni][0], acc[mi][ni][1]));
            rm1 = fmaxf(rm1, fmaxf(acc[mi][ni][2], acc[mi][ni][3]));
        }
        rm0 = fmaxf(rm0, __shfl_xor_sync(0xffffffffu, rm0, 1));
        rm0 = fmaxf(rm0, __shfl_xor_sync(0xffffffffu, rm0, 2));
        rm1 = fmaxf(rm1, __shfl_xor_sync(0xffffffffu, rm1, 1));
        rm1 = fmaxf(rm1, __shfl_xor_sync(0xffffffffu, rm1, 2));
        if ((lane & 3) == 0) {
            int r0 = wm * 96 + mi * 16 + (lane >> 2);
            atomicMax(&maxes[r0], enc_f(rm0));
            atomicMax(&maxes[r0 + 8], enc_f(rm1));
        }
    }
#pragma unroll
    for (int ni = 0; ni < 6; ni++) {
        float cm0 = -1e30f, cm1 = -1e30f;
#pragma unroll
        for (int mi = 0; mi < 6; mi++) {
            cm0 = fmaxf(cm0, fmaxf(acc[mi][ni][0], acc[mi][ni][2]));
            cm1 = fmaxf(cm1, fmaxf(acc[mi][ni][1], acc[mi][ni][3]));
        }
        cm0 = fmaxf(cm0, __shfl_xor_sync(0xffffffffu, cm0, 4));
        cm0 = fmaxf(cm0, __shfl_xor_sync(0xffffffffu, cm0, 8));
        cm0 = fmaxf(cm0, __shfl_xor_sync(0xffffffffu, cm0, 16));
        cm1 = fmaxf(cm1, __shfl_xor_sync(0xffffffffu, cm1, 4));
        cm1 = fmaxf(cm1, __shfl_xor_sync(0xffffffffu, cm1, 8));
        cm1 = fmaxf(cm1, __shfl_xor_sync(0xffffffffu, cm1, 16));
        if (lane < 4) {
            int c0 = wn * 48 + ni * 8 + lane * 2;
            atomicMax(&maxes[TM + c0], enc_f(cm0));
            atomicMax(&maxes[TM + c0 + 1], enc_f(cm1));
        }
    }
    __syncthreads();

    if (tid < TM) {
        int p = mt * TM + tid;
        atomicMax(&g_dotmax[((z * BN_IMG + b) * P_N + p) * BN_IMG + c], maxes[tid]);
        int q = nt * TN + tid;
        atomicMax(&g_dotmax[((z * BN_IMG + c) * P_N + q) * BN_IMG + b], maxes[TM + tid]);
    }
}

// ---------------- per-(z,b,p) top-2-smallest, atomicAdd into scores -------
__global__ void reduce_kernel() {
    int idx = blockIdx.x * blockDim.x + threadIdx.x;
    if (idx >= ZTOT * BN_IMG * P_N) return;
    int z = idx / (BN_IMG * P_N);
    int rowp = idx % (BN_IMG * P_N);
    int b = rowp / P_N;

    const unsigned* src = &g_dotmax[(size_t)idx * BN_IMG];
    float m1 = 1e30f, m2 = 1e30f;
#pragma unroll
    for (int c = 0; c < BN_IMG; c++) {
        if (c == b) continue;
        unsigned e = src[c];
        unsigned u = (e & 0x80000000u) ? (e & 0x7FFFFFFFu) : ~e;
        float dot = __uint_as_float(u);
        float d = sqrtf(fmaxf(2.f - 2.f * dot, 0.f));
        if (d < m1) { m2 = m1; m1 = d; }
        else if (d < m2) { m2 = d; }
    }
    atomicAdd(&g_scores[rowp], 0.5f * (m1 + m2) * (1.0f / (float)ZTOT));
    (void)z;
}

// ---------------- outputs ----------------
__global__ void image_kernel(float* __restrict__ out) {
    int b = blockIdx.x;
    int tid = threadIdx.x;
    float mx = -1e30f;
    for (int p = tid; p < P_N; p += blockDim.x)
        mx = fmaxf(mx, g_scores[b * P_N + p]);
#pragma unroll
    for (int o = 16; o > 0; o >>= 1)
        mx = fmaxf(mx, __shfl_xor_sync(0xffffffffu, mx, o));
    __shared__ float wm[8];
    if ((tid & 31) == 0) wm[tid >> 5] = mx;
    __syncthreads();
    if (tid == 0) {
        float m = wm[0];
        for (int w = 1; w < (int)(blockDim.x >> 5); w++) m = fmaxf(m, wm[w]);
        out[b] = m;
    }
}

__global__ void pixel_kernel(float* __restrict__ out) {
    int idx = blockIdx.x * blockDim.x + threadIdx.x;
    int total = BN_IMG * H_OUT * W_OUT;
    if (idx >= total) return;
    int ox = idx % W_OUT;
    int oy = (idx / W_OUT) % H_OUT;
    int b  = idx / (H_OUT * W_OUT);

    const float sy = (float)(PH - 1) / (float)(H_OUT - 1);
    const float sx = (float)(PW - 1) / (float)(W_OUT - 1);
    float y = oy * sy, x = ox * sx;
    int y0 = (int)floorf(y); int y1 = min(y0 + 1, PH - 1);
    int x0 = (int)floorf(x); int x1 = min(x0 + 1, PW - 1);
    float wy = y - (float)y0, wx = x - (float)x0;

    const float* s = g_scores + b * P_N;
    float f00 = s[y0 * PW + x0], f01 = s[y0 * PW + x1];
    float f10 = s[y1 * PW + x0], f11 = s[y1 * PW + x1];
    float v = f00 * (1.f - wy) * (1.f - wx) + f01 * (1.f - wy) * wx
            + f10 * wy * (1.f - wx)         + f11 * wy * wx;
    out[BN_IMG + idx] = v;
}

// ---------------- driver ----------------
extern "C" void kernel_launch(void* const* d_in, const int* in_sizes, int n_in,
                              void* d_out, int out_size) {
    (void)in_sizes; (void)n_in; (void)out_size;
    const float* feat = (const float*)d_in[0];
    float* out = (float*)d_out;

    cudaFuncSetAttribute(gemm_mma_kernel,
                         cudaFuncAttributeMaxDynamicSharedMemorySize, SMEM_TOTAL);

    zero_dot_kernel<<<(ZTOT * BN_IMG * P_N * BN_IMG + 255) / 256, 256>>>();
    pool_norm_fused<<<L_LAYERS * BN_IMG * PH, 256>>>(feat);

    // 2 launches (6 z each)
    gemm_mma_kernel<<<dim3(P_N / TN, P_N / TM, 6 * NPAIR), 256, SMEM_TOTAL>>>(0);
    gemm_mma_kernel<<<dim3(P_N / TN, P_N / TM, 6 * NPAIR), 256, SMEM_TOTAL>>>(6);

    reduce_kernel<<<(ZTOT * BN_IMG * P_N + 255) / 256, 256>>>();
    image_kernel<<<BN_IMG, 256>>>(out);
    pixel_kernel<<<(BN_IMG * H_OUT * W_OUT + 255) / 256, 256>>>(out);
}

// round 15
// speedup vs baseline: 1.0525x; 1.0071x over previous
#include <cuda_runtime.h>
#include <cuda_bf16.h>
#include <cstdint>

#define L_LAYERS 4
#define R_COUNT  3
#define ZTOT     (L_LAYERS * R_COUNT)   // 12
#define BN_IMG   8
#define NPAIR    28                     // unordered image pairs b<c
#define PH       24
#define PW       24
#define P_N      576
#define D_N      1024
#define H_OUT    336
#define W_OUT    336
#define M_TOT    4608

// CTA tile: M=192 x N=192, K-chunk 128 bf16 stored as two 64-col panels
// (128B rows, SW128). 8 warps (2x4), warp tile 96x48. 2-stage double buffer,
// R11 schedule (issue-load -> wait_group 1 -> sync -> compute -> sync).
#define TM 192
#define TN 192
#define KC 128
#define PANEL       24576                    // 192 rows * 128B
#define A_BYTES     (2 * PANEL)              // 49152
#define STAGE_BYTES (2 * A_BYTES)            // 98304
#define SMEM_MAXES  (2 * STAGE_BYTES)        // 196608
#define SMEM_TOTAL  (SMEM_MAXES + (TM + TN) * 4)

// ---------------- scratch ----------------
__device__ __nv_bfloat16 g_fnorm[(size_t)ZTOT * M_TOT * D_N];        // 108 MB
__device__ unsigned int  g_dotmax[ZTOT * BN_IMG * P_N * BN_IMG];
__device__ float         g_scores[BN_IMG * P_N];

// ---------------- helpers ----------------
__device__ __forceinline__ uint32_t smem_u32(const void* p) {
    uint32_t a;
    asm("{ .reg .u64 t; cvta.to.shared.u64 t, %1; cvt.u32.u64 %0, t; }"
        : "=r"(a) : "l"(p));
    return a;
}
#define SWZ128(o) ((o) ^ (((o) >> 3) & 0x70))

__device__ __forceinline__ void cp16(uint32_t dst, const void* src) {
    asm volatile("cp.async.cg.shared.global [%0], [%1], 16;"
                 :: "r"(dst), "l"(src) : "memory");
}
__device__ __forceinline__ void ldsm_x4(uint32_t (&r)[4], uint32_t addr) {
    asm volatile("ldmatrix.sync.aligned.m8n8.x4.shared.b16 {%0,%1,%2,%3}, [%4];"
                 : "=r"(r[0]), "=r"(r[1]), "=r"(r[2]), "=r"(r[3]) : "r"(addr));
}
__device__ __forceinline__ void mma16816(float* d, const uint32_t* a, const uint32_t* b) {
    asm volatile("mma.sync.aligned.m16n8k16.row.col.f32.bf16.bf16.f32 "
                 "{%0,%1,%2,%3}, {%4,%5,%6,%7}, {%8,%9}, {%0,%1,%2,%3};"
                 : "+f"(d[0]), "+f"(d[1]), "+f"(d[2]), "+f"(d[3])
                 : "r"(a[0]), "r"(a[1]), "r"(a[2]), "r"(a[3]), "r"(b[0]), "r"(b[1]));
}
__device__ __forceinline__ unsigned enc_f(float v) {
    unsigned u = __float_as_uint(v);
    return (u & 0x80000000u) ? ~u : (u | 0x80000000u);
}

// ---------------- zero init (dotmax + scores) ----------------
__global__ void zero_dot_kernel() {
    int i = blockIdx.x * blockDim.x + threadIdx.x;
    if (i < ZTOT * BN_IMG * P_N * BN_IMG) g_dotmax[i] = 0u;
    if (i < BN_IMG * P_N) g_scores[i] = 0.f;
}

// ---------------- fused pool (r=1,3,5) + normalize, sliding window --------
__device__ __forceinline__ void f4add(float4& a, const float4& f) {
    a.x += f.x; a.y += f.y; a.z += f.z; a.w += f.w;
}
__device__ __forceinline__ float f4dot(const float4& a) {
    return a.x * a.x + a.y * a.y + a.z * a.z + a.w * a.w;
}

__global__ void __launch_bounds__(256) pool_norm_fused(const float* __restrict__ feat) {
    __shared__ float sred[8 * 3];
    int bid = blockIdx.x;
    int l  = bid / (BN_IMG * PH);
    int rm = bid % (BN_IMG * PH);
    int b  = rm / PH;
    int py = rm % PH;
    const float* base = feat + (size_t)(l * BN_IMG + b) * P_N * D_N;

    int tid = threadIdx.x;
    int lane = tid & 31, w = tid >> 5;
    int d4 = tid * 4;

    float4 z4 = {0.f, 0.f, 0.f, 0.f};
    float4 ring5[5], ring3[5], ringc[5];
#pragma unroll
    for (int i = 0; i < 5; i++) { ring5[i] = z4; ring3[i] = z4; ringc[i] = z4; }

#pragma unroll
    for (int x = 0; x < PW + 2; x++) {        // px = x-2 in [0, PW)
        float4 c5 = z4, c3 = z4, cc = z4;
        if (x < PW) {
#pragma unroll
            for (int dy = -2; dy <= 2; dy++) {
                int y = py + dy;
                if (y < 0 || y >= PH) continue;
                float4 f = *(const float4*)&base[(size_t)(y * PW + x) * D_N + d4];
                f4add(c5, f);
                if (dy >= -1 && dy <= 1) f4add(c3, f);
                if (dy == 0) cc = f;
            }
        }
        ring5[x % 5] = c5; ring3[x % 5] = c3; ringc[x % 5] = cc;

        if (x >= 2) {
            int px = x - 2;
            float4 s5 = z4;
#pragma unroll
            for (int i = 0; i < 5; i++) f4add(s5, ring5[i]);
            float4 s3 = ring3[(x + 2) % 5];
            f4add(s3, ring3[(x + 3) % 5]);
            f4add(s3, ring3[(x + 4) % 5]);
            float4 s1 = ringc[(x + 3) % 5];

            float4 v3, v5;
            v3.x = s3.x * (1.f/9.f);  v3.y = s3.y * (1.f/9.f);
            v3.z = s3.z * (1.f/9.f);  v3.w = s3.w * (1.f/9.f);
            v5.x = s5.x * (1.f/25.f); v5.y = s5.y * (1.f/25.f);
            v5.z = s5.z * (1.f/25.f); v5.w = s5.w * (1.f/25.f);

            float q1 = f4dot(s1), q3 = f4dot(v3), q5 = f4dot(v5);
#pragma unroll
            for (int o = 16; o > 0; o >>= 1) {
                q1 += __shfl_xor_sync(0xffffffffu, q1, o);
                q3 += __shfl_xor_sync(0xffffffffu, q3, o);
                q5 += __shfl_xor_sync(0xffffffffu, q5, o);
            }
            if (lane == 0) { sred[w*3] = q1; sred[w*3+1] = q3; sred[w*3+2] = q5; }
            __syncthreads();
            float t1 = 0.f, t3 = 0.f, t5 = 0.f;
#pragma unroll
            for (int ww = 0; ww < 8; ww++) {
                t1 += sred[ww*3]; t3 += sred[ww*3+1]; t5 += sred[ww*3+2];
            }
            __syncthreads();
            float i1 = rsqrtf(t1), i3 = rsqrtf(t3), i5 = rsqrtf(t5);

            int row = b * P_N + py * PW + px;
            size_t off = (size_t)row * D_N + d4;
#pragma unroll
            for (int r = 0; r < 3; r++) {
                float4 v = (r == 0) ? s1 : (r == 1) ? v3 : v5;
                float sc = (r == 0) ? i1 : (r == 1) ? i3 : i5;
                __nv_bfloat162 lo(__float2bfloat16(v.x * sc), __float2bfloat16(v.y * sc));
                __nv_bfloat162 hi(__float2bfloat16(v.z * sc), __float2bfloat16(v.w * sc));
                uint2 pk;
                pk.x = *(uint32_t*)&lo; pk.y = *(uint32_t*)&hi;
                *(uint2*)(g_fnorm + (size_t)(r * L_LAYERS + l) * M_TOT * D_N + off) = pk;
            }
        }
    }
}

// ---------------- bf16 mma.sync GEMM over image pairs, fused row+col max --
__global__ void __launch_bounds__(256, 1) gemm_mma_kernel() {
    extern __shared__ char smem[];
    unsigned* maxes = (unsigned*)(smem + SMEM_MAXES);  // [0..TM) rowmax, [TM..TM+TN) colmax

    int bz = blockIdx.z;
    int pi = bz % NPAIR, z = bz / NPAIR;
    int b = 0;
    { int t = pi, rem = BN_IMG - 1;
      while (t >= rem) { t -= rem; rem--; b++; }
      pi = t; }
    int c = b + 1 + pi;

    int mt = blockIdx.y;    // 0..2
    int nt = blockIdx.x;    // 0..2

    const __nv_bfloat16* base = g_fnorm + (size_t)z * M_TOT * D_N;
    const __nv_bfloat16* Abase = base + (size_t)(b * P_N + mt * TM) * D_N;
    const __nv_bfloat16* Bbase = base + (size_t)(c * P_N + nt * TN) * D_N;

    int tid = threadIdx.x;
    int lane = tid & 31, wid = tid >> 5;
    int wm = wid >> 2, wn = wid & 3;       // 2 x 4 warp grid, warp tile 96x48
    uint32_t sbase = smem_u32(smem);

    for (int i = tid; i < TM + TN; i += 256) maxes[i] = 0u;

    float acc[6][6][4];
#pragma unroll
    for (int mi = 0; mi < 6; mi++)
#pragma unroll
        for (int ni = 0; ni < 6; ni++)
#pragma unroll
            for (int j = 0; j < 4; j++) acc[mi][ni][j] = 0.f;

    // one K=128 chunk = A[192x128] + B[192x128], each as two 64-col panels
    auto load_chunk = [&](int s, int k0) {
        uint32_t st = sbase + s * STAGE_BYTES;
#pragma unroll
        for (int it = 0; it < 24; it++) {
            int v = tid + it * 256;          // 0..6143
            if (v < 3072) {                  // A: 192 rows x 16 vec16
                int r = v >> 4, c16 = v & 15;
                uint32_t dst = st + (c16 >> 3) * PANEL
                             + SWZ128(r * 128 + (c16 & 7) * 16);
                cp16(dst, Abase + (size_t)r * D_N + k0 + c16 * 8);
            } else {
                int v2 = v - 3072;
                int r = v2 >> 4, c16 = v2 & 15;
                uint32_t dst = st + A_BYTES + (c16 >> 3) * PANEL
                             + SWZ128(r * 128 + (c16 & 7) * 16);
                cp16(dst, Bbase + (size_t)r * D_N + k0 + c16 * 8);
            }
        }
        asm volatile("cp.async.commit_group;" ::: "memory");
    };

    auto compute_chunk = [&](int s) {
        uint32_t stg = sbase + s * STAGE_BYTES;
        int arow = wm * 96 + (lane & 15);
        int aseg = (lane >> 4) * 16;
        int brow = wn * 48 + (lane & 7) + ((lane & 16) >> 1);   // x4 B
        int bseg = (lane & 8) * 2;
#pragma unroll
        for (int kk = 0; kk < 8; kk++) {
            uint32_t aB = stg + (kk >> 2) * PANEL;
            uint32_t bB = stg + A_BYTES + (kk >> 2) * PANEL;
            int kByte = (kk & 3) * 32;
            uint32_t a[6][4], bb[6][2];
#pragma unroll
            for (int mi = 0; mi < 6; mi++)
                ldsm_x4(a[mi], aB + SWZ128((arow + mi * 16) * 128 + kByte + aseg));
#pragma unroll
            for (int nj = 0; nj < 3; nj++) {
                uint32_t b4[4];
                ldsm_x4(b4, bB + SWZ128((brow + nj * 16) * 128 + kByte + bseg));
                bb[nj * 2][0] = b4[0]; bb[nj * 2][1] = b4[1];
                bb[nj * 2 + 1][0] = b4[2]; bb[nj * 2 + 1][1] = b4[3];
            }
#pragma unroll
            for (int mi = 0; mi < 6; mi++)
#pragma unroll
                for (int ni = 0; ni < 6; ni++)
                    mma16816(acc[mi][ni], a[mi], bb[ni]);
        }
    };

    // R11 schedule: issue next load, keep 1 group in flight across the barrier
    load_chunk(0, 0);
#pragma unroll 1
    for (int kc = 0; kc < 8; kc++) {
        int cur = kc & 1;
        if (kc + 1 < 8) {
            load_chunk(cur ^ 1, (kc + 1) * KC);
            asm volatile("cp.async.wait_group 1;" ::: "memory");
        } else {
            asm volatile("cp.async.wait_group 0;" ::: "memory");
        }
        __syncthreads();
        compute_chunk(cur);
        __syncthreads();
    }

    // ---- epilogue: row max over 192 cols, col max over 192 rows ----
#pragma unroll
    for (int mi = 0; mi < 6; mi++) {
        float rm0 = -1e30f, rm1 = -1e30f;
#pragma unroll
        for (int ni = 0; ni < 6; ni++) {
            rm0 = fmaxf(rm0, fmaxf(acc[mi][ni][0], acc[mi][ni][1]));
            rm1 = fmaxf(rm1, fmaxf(acc[mi][ni][2], acc[mi][ni][3]));
        }
        rm0 = fmaxf(rm0, __shfl_xor_sync(0xffffffffu, rm0, 1));
        rm0 = fmaxf(rm0, __shfl_xor_sync(0xffffffffu, rm0, 2));
        rm1 = fmaxf(rm1, __shfl_xor_sync(0xffffffffu, rm1, 1));
        rm1 = fmaxf(rm1, __shfl_xor_sync(0xffffffffu, rm1, 2));
        if ((lane & 3) == 0) {
            int r0 = wm * 96 + mi * 16 + (lane >> 2);
            atomicMax(&maxes[r0], enc_f(rm0));
            atomicMax(&maxes[r0 + 8], enc_f(rm1));
        }
    }
#pragma unroll
    for (int ni = 0; ni < 6; ni++) {
        float cm0 = -1e30f, cm1 = -1e30f;
#pragma unroll
        for (int mi = 0; mi < 6; mi++) {
            cm0 = fmaxf(cm0, fmaxf(acc[mi][ni][0], acc[mi][ni][2]));
            cm1 = fmaxf(cm1, fmaxf(acc[mi][ni][1], acc[mi][ni][3]));
        }
        cm0 = fmaxf(cm0, __shfl_xor_sync(0xffffffffu, cm0, 4));
        cm0 = fmaxf(cm0, __shfl_xor_sync(0xffffffffu, cm0, 8));
        cm0 = fmaxf(cm0, __shfl_xor_sync(0xffffffffu, cm0, 16));
        cm1 = fmaxf(cm1, __shfl_xor_sync(0xffffffffu, cm1, 4));
        cm1 = fmaxf(cm1, __shfl_xor_sync(0xffffffffu, cm1, 8));
        cm1 = fmaxf(cm1, __shfl_xor_sync(0xffffffffu, cm1, 16));
        if (lane < 4) {
            int c0 = wn * 48 + ni * 8 + lane * 2;
            atomicMax(&maxes[TM + c0], enc_f(cm0));
            atomicMax(&maxes[TM + c0 + 1], enc_f(cm1));
        }
    }
    __syncthreads();

    if (tid < TM) {
        int p = mt * TM + tid;
        atomicMax(&g_dotmax[((z * BN_IMG + b) * P_N + p) * BN_IMG + c], maxes[tid]);
        int q = nt * TN + tid;
        atomicMax(&g_dotmax[((z * BN_IMG + c) * P_N + q) * BN_IMG + b], maxes[TM + tid]);
    }
}

// ---------------- per-(z,b,p) top-2-smallest, atomicAdd into scores -------
__global__ void reduce_kernel() {
    int idx = blockIdx.x * blockDim.x + threadIdx.x;
    if (idx >= ZTOT * BN_IMG * P_N) return;
    int rowp = idx % (BN_IMG * P_N);
    int b = rowp / P_N;

    const unsigned* src = &g_dotmax[(size_t)idx * BN_IMG];
    float m1 = 1e30f, m2 = 1e30f;
#pragma unroll
    for (int c = 0; c < BN_IMG; c++) {
        if (c == b) continue;
        unsigned e = src[c];
        unsigned u = (e & 0x80000000u) ? (e & 0x7FFFFFFFu) : ~e;
        float dot = __uint_as_float(u);
        float d = sqrtf(fmaxf(2.f - 2.f * dot, 0.f));
        if (d < m1) { m2 = m1; m1 = d; }
        else if (d < m2) { m2 = d; }
    }
    atomicAdd(&g_scores[rowp], 0.5f * (m1 + m2) * (1.0f / (float)ZTOT));
}

// ---------------- outputs ----------------
__global__ void image_kernel(float* __restrict__ out) {
    int b = blockIdx.x;
    int tid = threadIdx.x;
    float mx = -1e30f;
    for (int p = tid; p < P_N; p += blockDim.x)
        mx = fmaxf(mx, g_scores[b * P_N + p]);
#pragma unroll
    for (int o = 16; o > 0; o >>= 1)
        mx = fmaxf(mx, __shfl_xor_sync(0xffffffffu, mx, o));
    __shared__ float wm[8];
    if ((tid & 31) == 0) wm[tid >> 5] = mx;
    __syncthreads();
    if (tid == 0) {
        float m = wm[0];
        for (int w = 1; w < (int)(blockDim.x >> 5); w++) m = fmaxf(m, wm[w]);
        out[b] = m;
    }
}

__global__ void pixel_kernel(float* __restrict__ out) {
    int idx = blockIdx.x * blockDim.x + threadIdx.x;
    int total = BN_IMG * H_OUT * W_OUT;
    if (idx >= total) return;
    int ox = idx % W_OUT;
    int oy = (idx / W_OUT) % H_OUT;
    int b  = idx / (H_OUT * W_OUT);

    const float sy = (float)(PH - 1) / (float)(H_OUT - 1);
    const float sx = (float)(PW - 1) / (float)(W_OUT - 1);
    float y = oy * sy, x = ox * sx;
    int y0 = (int)floorf(y); int y1 = min(y0 + 1, PH - 1);
    int x0 = (int)floorf(x); int x1 = min(x0 + 1, PW - 1);
    float wy = y - (float)y0, wx = x - (float)x0;

    const float* s = g_scores + b * P_N;
    float f00 = s[y0 * PW + x0], f01 = s[y0 * PW + x1];
    float f10 = s[y1 * PW + x0], f11 = s[y1 * PW + x1];
    float v = f00 * (1.f - wy) * (1.f - wx) + f01 * (1.f - wy) * wx
            + f10 * wy * (1.f - wx)         + f11 * wy * wx;
    out[BN_IMG + idx] = v;
}

// ---------------- driver ----------------
extern "C" void kernel_launch(void* const* d_in, const int* in_sizes, int n_in,
                              void* d_out, int out_size) {
    (void)in_sizes; (void)n_in; (void)out_size;
    const float* feat = (const float*)d_in[0];
    float* out = (float*)d_out;

    cudaFuncSetAttribute(gemm_mma_kernel,
                         cudaFuncAttributeMaxDynamicSharedMemorySize, SMEM_TOTAL);

    zero_dot_kernel<<<(ZTOT * BN_IMG * P_N * BN_IMG + 255) / 256, 256>>>();
    pool_norm_fused<<<L_LAYERS * BN_IMG * PH, 256>>>(feat);

    // single GEMM launch: one tail wave instead of two
    gemm_mma_kernel<<<dim3(P_N / TN, P_N / TM, ZTOT * NPAIR), 256, SMEM_TOTAL>>>();

    reduce_kernel<<<(ZTOT * BN_IMG * P_N + 255) / 256, 256>>>();
    image_kernel<<<BN_IMG, 256>>>(out);
    pixel_kernel<<<(BN_IMG * H_OUT * W_OUT + 255) / 256, 256>>>(out);
}